// round 13
// baseline (speedup 1.0000x reference)
#include <cuda_runtime.h>
#include <cstdint>

// DeepMapping2D occupancy_generation, GB300 sm_103a.  Round 13.
//
//   output[b] = K_b ones then zeros, K_b = #bins with count >= 53.
//   Min-shift is a bin bijection -> K_b shift-invariant -> no min pass.
//
// Validated model (R4-R12):
//   * hist pinned at the LTS sector-RMW cap (~95us). REDG only; no returns
//     (R6 +44us); no extra MLP (R5); no stream forks (R9). DO NOT TOUCH.
//   * re-zero via cudaMemsetAsync (R12: ~5us, beats store kernel's 10us).
//   * count measured ~9us vs ~5.7us traffic floor -> latency-exposure gap.
// R13: count restructured to grid (16,64) x 256, 16 uint4/thread, loads
// front-batched in groups of 4 before any consumption (deep per-thread MLP,
// clean wave structure). Everything else byte-identical to R12.

#define NBATCH  64
#define NPTS    262144
#define TOPK    5120
#define GZ_LOG2 10
#define BINS_PER_BATCH   (1024u * 1024u)          // 1M u8 bins / batch
#define HWORDS_PER_BATCH (BINS_PER_BATCH / 4)     // 256K u32 / batch

__device__ unsigned int g_hist[(size_t)NBATCH * HWORDS_PER_BATCH];  // 64 MB, load-zeroed
__device__ unsigned int g_count[NBATCH];                            // load-zeroed

// ---------------------------------------------------------------------------
// Kernel 1: histogram scatter, RED-only byte adds + per-batch counter reset.
// grid (64, 64) x 256 thr; grid-stride, unroll 4. Measured 94-96us.
// ---------------------------------------------------------------------------
__global__ void dm2d_hist_kernel(const float4* __restrict__ pcd) {
    const int b = blockIdx.y;
    if (blockIdx.x == 0 && threadIdx.x == 0)
        g_count[b] = 0u;                           // reset (prev replay's value)

    unsigned int* __restrict__ hist = g_hist + (size_t)b * HWORDS_PER_BATCH;
    const float4* __restrict__ base = pcd + (size_t)b * (NPTS / 2);

    const int tid    = blockIdx.x * blockDim.x + threadIdx.x;
    const int stride = gridDim.x * blockDim.x;

    #pragma unroll 4
    for (int i = tid; i < NPTS / 2; i += stride) {
        float4 p = __ldcs(&base[i]);   // two points: (x0,z0,x1,z1); evict-first

        // jnp.round = round-half-to-even == rintf under default RN mode.
        unsigned x0 = (unsigned)(int)rintf(1000.0f * p.x);
        unsigned z0 = (unsigned)(int)rintf(1000.0f * p.y);
        unsigned x1 = (unsigned)(int)rintf(1000.0f * p.z);
        unsigned z1 = (unsigned)(int)rintf(1000.0f * p.w);

        unsigned i0 = (x0 << GZ_LOG2) | z0;
        unsigned i1 = (x1 << GZ_LOG2) | z1;

        // fire-and-forget byte increments (return unused -> REDG)
        atomicAdd(&hist[i0 >> 2], 1u << ((i0 & 3u) << 3));
        atomicAdd(&hist[i1 >> 2], 1u << ((i1 & 3u) << 3));
    }
}

// ---------------------------------------------------------------------------
// Kernel 2: count bins >= 53 per batch. READ-ONLY.
// grid (16, 64) x 256 thr; 16 uint4 = 256 bins per thread, loads
// front-batched 4-at-a-time before consumption.
// ---------------------------------------------------------------------------
__global__ void dm2d_count_kernel() {
    const int b = blockIdx.y;
    const uint4* __restrict__ hist4 =
        reinterpret_cast<const uint4*>(g_hist + (size_t)b * HWORDS_PER_BATCH);

    const int tid = blockIdx.x * 256 + threadIdx.x;   // 0..4095

    unsigned int cnt = 0;
    #pragma unroll
    for (int g = 0; g < 4; g++) {
        uint4 w0 = hist4[tid + (g * 4 + 0) * 4096];   // front-batched group
        uint4 w1 = hist4[tid + (g * 4 + 1) * 4096];
        uint4 w2 = hist4[tid + (g * 4 + 2) * 4096];
        uint4 w3 = hist4[tid + (g * 4 + 3) * 4096];

        cnt += __popc(__vcmpgeu4(w0.x, 0x35353535u) & 0x01010101u);
        cnt += __popc(__vcmpgeu4(w0.y, 0x35353535u) & 0x01010101u);
        cnt += __popc(__vcmpgeu4(w0.z, 0x35353535u) & 0x01010101u);
        cnt += __popc(__vcmpgeu4(w0.w, 0x35353535u) & 0x01010101u);
        cnt += __popc(__vcmpgeu4(w1.x, 0x35353535u) & 0x01010101u);
        cnt += __popc(__vcmpgeu4(w1.y, 0x35353535u) & 0x01010101u);
        cnt += __popc(__vcmpgeu4(w1.z, 0x35353535u) & 0x01010101u);
        cnt += __popc(__vcmpgeu4(w1.w, 0x35353535u) & 0x01010101u);
        cnt += __popc(__vcmpgeu4(w2.x, 0x35353535u) & 0x01010101u);
        cnt += __popc(__vcmpgeu4(w2.y, 0x35353535u) & 0x01010101u);
        cnt += __popc(__vcmpgeu4(w2.z, 0x35353535u) & 0x01010101u);
        cnt += __popc(__vcmpgeu4(w2.w, 0x35353535u) & 0x01010101u);
        cnt += __popc(__vcmpgeu4(w3.x, 0x35353535u) & 0x01010101u);
        cnt += __popc(__vcmpgeu4(w3.y, 0x35353535u) & 0x01010101u);
        cnt += __popc(__vcmpgeu4(w3.z, 0x35353535u) & 0x01010101u);
        cnt += __popc(__vcmpgeu4(w3.w, 0x35353535u) & 0x01010101u);
    }

    #pragma unroll
    for (int off = 16; off > 0; off >>= 1)
        cnt += __shfl_down_sync(0xFFFFFFFFu, cnt, off);
    if ((threadIdx.x & 31) == 0 && cnt)
        atomicAdd(&g_count[b], cnt);
}

// ---------------------------------------------------------------------------
// Kernel 3: output expansion, distributed float4 writes.
// grid (5, 64) x 256 thr: 1280 float4 = 5120 floats per batch.
// ---------------------------------------------------------------------------
__global__ void dm2d_out_kernel(float* __restrict__ out) {
    const int b = blockIdx.y;
    const int tid = blockIdx.x * 256 + threadIdx.x;   // 0..1279
    const int K = (int)g_count[b];
    const int i = tid * 4;
    float4 v;
    v.x = (i + 0 < K) ? 1.0f : 0.0f;
    v.y = (i + 1 < K) ? 1.0f : 0.0f;
    v.z = (i + 2 < K) ? 1.0f : 0.0f;
    v.w = (i + 3 < K) ? 1.0f : 0.0f;
    reinterpret_cast<float4*>(out + (size_t)b * TOPK)[tid] = v;
}

extern "C" void kernel_launch(void* const* d_in, const int* in_sizes, int n_in,
                              void* d_out, int out_size) {
    (void)in_sizes; (void)n_in; (void)out_size;
    const float4* pcd = reinterpret_cast<const float4*>(d_in[0]);
    float* out = reinterpret_cast<float*>(d_out);

    dm2d_hist_kernel<<<dim3(64, NBATCH), 256>>>(pcd);
    dm2d_count_kernel<<<dim3(16, NBATCH), 256>>>();
    dm2d_out_kernel<<<dim3(5, NBATCH), 256>>>(out);

    // Re-zero the histogram for the next replay (driver-tuned write path).
    void* hist_ptr = nullptr;
    cudaGetSymbolAddress(&hist_ptr, g_hist);
    cudaMemsetAsync(hist_ptr, 0, (size_t)NBATCH * BINS_PER_BATCH, 0);
}